// round 12
// baseline (speedup 1.0000x reference)
#include <cuda_runtime.h>
#include <cuda_fp16.h>
#include <math_constants.h>
#include <cstdint>

#define BB 8
#define TT 2048
#define CC 1024
#define HH 64
#define MM (BB*TT)          // 16384 rows

// scratch (device globals — no allocation allowed)
__device__ float g_q[(size_t)MM*HH];
__device__ float g_k[(size_t)MM*HH];
__device__ float g_v[(size_t)MM*HH];
// fp16 weights, transposed [(o*64+n)*1024 + kperm], k frag-permuted per 16-group
__device__ __align__(16) __half g_wth[3*64*1024];
// split-K attention partials (4 splits)
__device__ float g_po[4*(size_t)MM*HH];
__device__ float g_pm[4*MM];
__device__ float g_pl[4*MM];

// ---------------------------------------------------------------------------
// mma.sync wrappers (plain PTX, sm_80+, works on sm_103 non-'a' target)
// ---------------------------------------------------------------------------
__device__ __forceinline__ void mma_fp16(float* c, const uint32_t* a, const uint32_t* b) {
    asm volatile(
        "mma.sync.aligned.m16n8k16.row.col.f32.f16.f16.f32 "
        "{%0,%1,%2,%3},{%4,%5,%6,%7},{%8,%9},{%0,%1,%2,%3};"
        : "+f"(c[0]), "+f"(c[1]), "+f"(c[2]), "+f"(c[3])
        : "r"(a[0]), "r"(a[1]), "r"(a[2]), "r"(a[3]), "r"(b[0]), "r"(b[1]));
}
__device__ __forceinline__ void mma_tf32(float* c, const uint32_t* a, const uint32_t* b) {
    asm volatile(
        "mma.sync.aligned.m16n8k8.row.col.f32.tf32.tf32.f32 "
        "{%0,%1,%2,%3},{%4,%5,%6,%7},{%8,%9},{%0,%1,%2,%3};"
        : "+f"(c[0]), "+f"(c[1]), "+f"(c[2]), "+f"(c[3])
        : "r"(a[0]), "r"(a[1]), "r"(a[2]), "r"(a[3]), "r"(b[0]), "r"(b[1]));
}
__device__ __forceinline__ uint32_t f2tf32(float f) {
    uint32_t r;
    asm("cvt.rna.tf32.f32 %0, %1;" : "=r"(r) : "f"(f));
    return r;
}
// exact fp16 two-term split of (x0, x1)
__device__ __forceinline__ void split2h(float x0, float x1, uint32_t& hi, uint32_t& lo) {
    __half h0 = __float2half_rn(x0), h1 = __float2half_rn(x1);
    __half l0 = __float2half_rn(x0 - __half2float(h0));
    __half l1 = __float2half_rn(x1 - __half2float(h1));
    __half2 ph = __halves2half2(h0, h1);
    __half2 pl = __halves2half2(l0, l1);
    hi = *(uint32_t*)&ph;
    lo = *(uint32_t*)&pl;
}
__device__ __forceinline__ uint32_t smem_to_u32(const void* smem_ptr) {
    uint32_t addr;
    asm("{ .reg .u64 tmp; cvta.to.shared.u64 tmp, %1; cvt.u32.u64 %0, tmp; }"
        : "=r"(addr) : "l"(smem_ptr));
    return addr;
}
#define CP_ASYNC16(saddr, gptr) \
    asm volatile("cp.async.cg.shared.global [%0], [%1], 16;" \
                 :: "r"(saddr), "l"(gptr) : "memory")
#define CP_COMMIT() asm volatile("cp.async.commit_group;" ::: "memory")
#define CP_WAIT0()  asm volatile("cp.async.wait_group 0;" ::: "memory")

// ---------------------------------------------------------------------------
// Weight prep: W[1024,64] (x3) -> fp16, transposed [n][k], k permuted within
// each 16-group to frag order [2t,2t+1,2t+8,2t+9] (slots 4t..4t+3) so the proj
// b-fragment is one LDS.64.
// ---------------------------------------------------------------------------
__global__ __launch_bounds__(256) void wsplit_kernel(
    const float* __restrict__ Wq, const float* __restrict__ Wk, const float* __restrict__ Wv)
{
    __shared__ uint32_t tsm[32][33];
    const int o   = blockIdx.x >> 6;
    const int rem = blockIdx.x & 63;
    const int kt  = rem & 31;
    const int nt2 = rem >> 5;
    const int k0  = kt * 32;
    const int n0  = nt2 * 32;
    const int tx  = threadIdx.x & 31;
    const int ty  = threadIdx.x >> 5;
    const float* W = (o == 0) ? Wq : ((o == 1) ? Wk : Wv);

    #pragma unroll
    for (int i = 0; i < 4; i++) {
        int k = k0 + ty + i * 8;
        float v = W[(size_t)k * 64 + n0 + tx];
        tsm[ty + i * 8][tx] = (uint32_t)__half_as_ushort(__float2half_rn(v));
    }
    __syncthreads();
    uint16_t* wh = (uint16_t*)g_wth;
    const int k16  = tx & 15;
    const int slot = ((k16 & 7) >> 1) * 4 + ((k16 >> 3) & 1) * 2 + (k16 & 1);
    const int kperm = k0 + (tx & 16) + slot;
    #pragma unroll
    for (int i = 0; i < 4; i++) {
        int n = n0 + ty + i * 8;
        wh[((size_t)o * 64 + n) * 1024 + kperm] = (uint16_t)tsm[tx][ty + i * 8];
    }
}

// ---------------------------------------------------------------------------
// Projection via mma.sync 2-term fp16 split:
//   q|k|v = (xh + xl) @ fp16(W)   (x split exact; only W rounding error)
// 256 CTAs x 256 threads (8 warps: 4M x 2N). CTA owns 64 rows; warp (wm,wn)
// owns rows wm*16..+15 x cols wn*96..+95. K in 16 chunks of 64; A prefetched.
// smem: AH[64][72]h @0, AL @9216, BH[192][72]h @18432 (frag-permuted k).
// ---------------------------------------------------------------------------
#define PROJ_SMEM 46080

__global__ __launch_bounds__(256, 2) void proj_mma_kernel(const float* __restrict__ x)
{
    extern __shared__ char psm[];
    __half* AH = (__half*)(psm);
    __half* AL = (__half*)(psm + 9216);
    __half* BH = (__half*)(psm + 18432);

    const int tid = threadIdx.x;
    const int w   = tid >> 5;
    const int l   = tid & 31;
    const int g   = l >> 2;
    const int t   = l & 3;
    const int wm  = w >> 1;
    const int wn  = w & 1;
    const int m0  = blockIdx.x * 64;

    float acc[12][4];
    #pragma unroll
    for (int nt = 0; nt < 12; nt++)
        #pragma unroll
        for (int j = 0; j < 4; j++) acc[nt][j] = 0.f;

    float4 apre[4];
    #pragma unroll
    for (int p = 0; p < 4; p++) {
        int i   = p * 256 + tid;
        int row = i >> 4, c4 = i & 15;
        apre[p] = *(const float4*)&x[(size_t)(m0 + row) * CC + c4 * 4];
    }

    for (int c = 0; c < 16; c++) {
        const int kk = c * 64;
        __syncthreads();

        // stage A (fp16 hi/lo, physical k order)
        #pragma unroll
        for (int p = 0; p < 4; p++) {
            int i   = p * 256 + tid;
            int row = i >> 4, c4 = i & 15;
            uint32_t h01, l01, h23, l23;
            split2h(apre[p].x, apre[p].y, h01, l01);
            split2h(apre[p].z, apre[p].w, h23, l23);
            *(uint2*)&AH[row * 72 + c4 * 4] = make_uint2(h01, h23);
            *(uint2*)&AL[row * 72 + c4 * 4] = make_uint2(l01, l23);
        }
        // stage B (linear copy; permutation already applied in gmem)
        #pragma unroll
        for (int it = 0; it < 6; it++) {
            int i  = it * 256 + tid;       // 0..1535 uint4s
            int n  = i >> 3, k8 = i & 7;
            *(uint4*)&BH[n * 72 + k8 * 8] =
                *(const uint4*)&((const __half*)g_wth)[(size_t)n * 1024 + kk + k8 * 8];
        }
        __syncthreads();

        if (c < 15) {
            #pragma unroll
            for (int p = 0; p < 4; p++) {
                int i   = p * 256 + tid;
                int row = i >> 4, c4 = i & 15;
                apre[p] = *(const float4*)&x[(size_t)(m0 + row) * CC + kk + 64 + c4 * 4];
            }
        }

        const int arow = wm * 16 + g;
        #pragma unroll
        for (int ks = 0; ks < 4; ks++) {
            const int kbase = ks * 16 + 2 * t;
            uint32_t ah[4], al_[4];
            ah[0]  = *(const uint32_t*)&AH[(arow    ) * 72 + kbase    ];
            ah[1]  = *(const uint32_t*)&AH[(arow + 8) * 72 + kbase    ];
            ah[2]  = *(const uint32_t*)&AH[(arow    ) * 72 + kbase + 8];
            ah[3]  = *(const uint32_t*)&AH[(arow + 8) * 72 + kbase + 8];
            al_[0] = *(const uint32_t*)&AL[(arow    ) * 72 + kbase    ];
            al_[1] = *(const uint32_t*)&AL[(arow + 8) * 72 + kbase    ];
            al_[2] = *(const uint32_t*)&AL[(arow    ) * 72 + kbase + 8];
            al_[3] = *(const uint32_t*)&AL[(arow + 8) * 72 + kbase + 8];
            #pragma unroll
            for (int nt = 0; nt < 12; nt++) {
                const int brow = wn * 96 + nt * 8 + g;
                uint2 bb = *(const uint2*)&BH[brow * 72 + ks * 16 + t * 4];
                uint32_t bh[2] = {bb.x, bb.y};
                mma_fp16(acc[nt], ah, bh);
                mma_fp16(acc[nt], al_, bh);
            }
        }
    }

    const int r0 = m0 + wm * 16 + g;
    #pragma unroll
    for (int nt = 0; nt < 12; nt++) {
        int base = wn * 96 + nt * 8;
        int o    = base >> 6;
        int col  = (base & 63) + 2 * t;
        float* dst = (o == 0) ? g_q : ((o == 1) ? g_k : g_v);
        *(float2*)&dst[(size_t)r0 * HH + col]       = make_float2(acc[nt][0], acc[nt][1]);
        *(float2*)&dst[(size_t)(r0 + 8) * HH + col] = make_float2(acc[nt][2], acc[nt][3]);
    }
}

// ---------------------------------------------------------------------------
// Attention: tf32 mma.sync, 128x64 tiles, cp.async pipelined K/V,
// balanced pairing (p, 15-p) x split-4 -> 256 blocks x 256 threads.
// K stored h-permuted (pairs (t, t+4) adjacent) -> kb is one LDS.64.
// smem (u32): Qs[128][68] (Q frags + P), Ks[64][68], Vs[64][72],
//             rawK[4096], rawV[4096]  -> 103424 B.
// ---------------------------------------------------------------------------
#define ATTN_SMEM 103424

__global__ __launch_bounds__(256, 2) void attn_kernel(const float* __restrict__ rbias)
{
    extern __shared__ uint32_t sm[];
    uint32_t* Qs   = sm;                       // [128][68], also P staging
    uint32_t* Ks   = sm + 128 * 68;
    uint32_t* Vs   = Ks + 64 * 68;
    uint32_t* rawK = Vs + 64 * 72;
    uint32_t* rawV = rawK + 4096;
    const uint32_t smem_base = smem_to_u32(sm);
    const uint32_t rawK_addr = smem_base + 17664u * 4u;
    const uint32_t rawV_addr = rawK_addr + 16384u;

    const int tid   = threadIdx.x;
    const int w     = tid >> 5;
    const int l     = tid & 31;
    const int g     = l >> 2;
    const int t     = l & 3;
    const int s     = blockIdx.x & 3;
    const int idx   = blockIdx.x >> 2;
    const int pairp = idx >> 3;        // 0..7
    const int b     = idx & 7;

    const float* qg = g_q + (size_t)b * TT * HH;
    const float* kg = g_k + (size_t)b * TT * HH;
    const float* vg = g_v + (size_t)b * TT * HH;
    const float scale = 0.03125f;   // C^-0.5

    for (int rep = 0; rep < 2; rep++) {
        const int itile = rep ? (15 - pairp) : pairp;
        const int i0    = itile * 128;
        const int nfull = 2 * itile + 2;
        const int jt_begin = (s * nfull) >> 2;
        const int jt_end   = ((s + 1) * nfull) >> 2;

        __syncthreads();   // Qs (P) reuse across reps
        #pragma unroll
        for (int it = 0; it < 8; it++) {
            int i = it * 256 + tid;
            int row = i >> 4, c4 = i & 15;
            float4 v = *(const float4*)&qg[(size_t)(i0 + row) * HH + c4 * 4];
            uint4 u;
            u.x = f2tf32(v.x); u.y = f2tf32(v.y); u.z = f2tf32(v.z); u.w = f2tf32(v.w);
            *(uint4*)&Qs[row * 68 + c4 * 4] = u;
        }
        __syncthreads();

        uint32_t qa[8][4];
        {
            const int qrow = w * 16 + g;
            #pragma unroll
            for (int ks = 0; ks < 8; ks++) {
                qa[ks][0] = Qs[(qrow    ) * 68 + ks * 8 + t    ];
                qa[ks][1] = Qs[(qrow + 8) * 68 + ks * 8 + t    ];
                qa[ks][2] = Qs[(qrow    ) * 68 + ks * 8 + t + 4];
                qa[ks][3] = Qs[(qrow + 8) * 68 + ks * 8 + t + 4];
            }
        }

        float o[8][4];
        #pragma unroll
        for (int nt = 0; nt < 8; nt++)
            #pragma unroll
            for (int j = 0; j < 4; j++) o[nt][j] = 0.f;
        float m0r = -CUDART_INF_F, m1r = -CUDART_INF_F, l0r = 0.f, l1r = 0.f;

        const int gi0 = i0 + w * 16 + g;
        const int gi1 = gi0 + 8;
        const int prow0 = (w * 16 + g) * 68;
        const int prow1 = prow0 + 8 * 68;

        if (jt_begin < jt_end) {
            const float* kp = kg + (size_t)jt_begin * 64 * HH;
            const float* vp = vg + (size_t)jt_begin * 64 * HH;
            #pragma unroll
            for (int p = 0; p < 4; p++) {
                int i = p * 256 + tid;
                CP_ASYNC16(rawK_addr + i * 16, kp + i * 4);
                CP_ASYNC16(rawV_addr + i * 16, vp + i * 4);
            }
            CP_COMMIT();
        }

        for (int jt = jt_begin; jt < jt_end; jt++) {
            const int j0 = jt * 64;
            CP_WAIT0();
            __syncthreads();
            // stage raw -> tf32: K h-permuted (pairs (t,t+4) adjacent), V direct
            #pragma unroll
            for (int it = 0; it < 4; it++) {
                int i = it * 256 + tid;
                int row = i >> 4, c4 = i & 15;
                uint4 kq = *(uint4*)&rawK[i * 4];
                int rowoff = row * 68 + 8 * (c4 >> 1) + (c4 & 1);
                Ks[rowoff + 0] = f2tf32(__uint_as_float(kq.x));
                Ks[rowoff + 2] = f2tf32(__uint_as_float(kq.y));
                Ks[rowoff + 4] = f2tf32(__uint_as_float(kq.z));
                Ks[rowoff + 6] = f2tf32(__uint_as_float(kq.w));
                uint4 vq = *(uint4*)&rawV[i * 4];
                uint4 vo;
                vo.x = f2tf32(__uint_as_float(vq.x)); vo.y = f2tf32(__uint_as_float(vq.y));
                vo.z = f2tf32(__uint_as_float(vq.z)); vo.w = f2tf32(__uint_as_float(vq.w));
                *(uint4*)&Vs[row * 72 + c4 * 4] = vo;
            }
            __syncthreads();
            if (jt + 1 < jt_end) {
                const float* kp = kg + (size_t)(jt + 1) * 64 * HH;
                const float* vp = vg + (size_t)(jt + 1) * 64 * HH;
                #pragma unroll
                for (int p = 0; p < 4; p++) {
                    int i = p * 256 + tid;
                    CP_ASYNC16(rawK_addr + i * 16, kp + i * 4);
                    CP_ASYNC16(rawV_addr + i * 16, vp + i * 4);
                }
                CP_COMMIT();
            }

            // S = Q K^T   (kb = one LDS.64 thanks to h-permutation)
            float sv[8][4];
            #pragma unroll
            for (int nt = 0; nt < 8; nt++) {
                sv[nt][0] = 0.f; sv[nt][1] = 0.f; sv[nt][2] = 0.f; sv[nt][3] = 0.f;
                #pragma unroll
                for (int ks = 0; ks < 8; ks++) {
                    uint2 kbv = *(const uint2*)&Ks[(nt * 8 + g) * 68 + ks * 8 + 2 * t];
                    uint32_t kb[2] = {kbv.x, kbv.y};
                    mma_tf32(sv[nt], qa[ks], kb);
                }
            }

            // bias + mask + row max
            float rm0 = -CUDART_INF_F, rm1 = -CUDART_INF_F;
            #pragma unroll
            for (int nt = 0; nt < 8; nt++) {
                int cj = j0 + nt * 8 + 2 * t;
                float2 rb0 = *(const float2*)&rbias[(size_t)gi0 * TT + cj];
                float2 rb1 = *(const float2*)&rbias[(size_t)gi1 * TT + cj];
                bool ok;
                ok = (cj     < gi0 && rb0.x > 0.f) || (cj     == gi0);
                sv[nt][0] = ok ? fmaf(sv[nt][0], scale, rb0.x) : -CUDART_INF_F;
                ok = (cj + 1 < gi0 && rb0.y > 0.f) || (cj + 1 == gi0);
                sv[nt][1] = ok ? fmaf(sv[nt][1], scale, rb0.y) : -CUDART_INF_F;
                ok = (cj     < gi1 && rb1.x > 0.f) || (cj     == gi1);
                sv[nt][2] = ok ? fmaf(sv[nt][2], scale, rb1.x) : -CUDART_INF_F;
                ok = (cj + 1 < gi1 && rb1.y > 0.f) || (cj + 1 == gi1);
                sv[nt][3] = ok ? fmaf(sv[nt][3], scale, rb1.y) : -CUDART_INF_F;
                rm0 = fmaxf(rm0, fmaxf(sv[nt][0], sv[nt][1]));
                rm1 = fmaxf(rm1, fmaxf(sv[nt][2], sv[nt][3]));
            }
            rm0 = fmaxf(rm0, __shfl_xor_sync(0xffffffffu, rm0, 1));
            rm0 = fmaxf(rm0, __shfl_xor_sync(0xffffffffu, rm0, 2));
            rm1 = fmaxf(rm1, __shfl_xor_sync(0xffffffffu, rm1, 1));
            rm1 = fmaxf(rm1, __shfl_xor_sync(0xffffffffu, rm1, 2));

            float mn0 = fmaxf(m0r, rm0), mn1 = fmaxf(m1r, rm1);
            float mu0 = (mn0 == -CUDART_INF_F) ? 0.f : mn0;
            float mu1 = (mn1 == -CUDART_INF_F) ? 0.f : mn1;
            float a0 = __expf(m0r - mu0), a1 = __expf(m1r - mu1);
            float rs0 = 0.f, rs1 = 0.f;
            #pragma unroll
            for (int nt = 0; nt < 8; nt++) {
                sv[nt][0] = __expf(sv[nt][0] - mu0); rs0 += sv[nt][0];
                sv[nt][1] = __expf(sv[nt][1] - mu0); rs0 += sv[nt][1];
                sv[nt][2] = __expf(sv[nt][2] - mu1); rs1 += sv[nt][2];
                sv[nt][3] = __expf(sv[nt][3] - mu1); rs1 += sv[nt][3];
            }
            rs0 += __shfl_xor_sync(0xffffffffu, rs0, 1);
            rs0 += __shfl_xor_sync(0xffffffffu, rs0, 2);
            rs1 += __shfl_xor_sync(0xffffffffu, rs1, 1);
            rs1 += __shfl_xor_sync(0xffffffffu, rs1, 2);
            l0r = l0r * a0 + rs0;  m0r = mn0;
            l1r = l1r * a1 + rs1;  m1r = mn1;

            #pragma unroll
            for (int nt = 0; nt < 8; nt++) {
                o[nt][0] *= a0; o[nt][1] *= a0; o[nt][2] *= a1; o[nt][3] *= a1;
                int pc = nt * 8 + 2 * t;
                Qs[prow0 + pc]     = f2tf32(sv[nt][0]);
                Qs[prow0 + pc + 1] = f2tf32(sv[nt][1]);
                Qs[prow1 + pc]     = f2tf32(sv[nt][2]);
                Qs[prow1 + pc + 1] = f2tf32(sv[nt][3]);
            }
            __syncwarp();

            // O += P @ V
            #pragma unroll
            for (int ks = 0; ks < 8; ks++) {
                uint32_t pa[4];
                pa[0] = Qs[prow0 + ks * 8 + t    ];
                pa[1] = Qs[prow1 + ks * 8 + t    ];
                pa[2] = Qs[prow0 + ks * 8 + t + 4];
                pa[3] = Qs[prow1 + ks * 8 + t + 4];
                #pragma unroll
                for (int nt = 0; nt < 8; nt++) {
                    uint32_t vb[2];
                    vb[0] = Vs[(ks * 8 + t    ) * 72 + nt * 8 + g];
                    vb[1] = Vs[(ks * 8 + t + 4) * 72 + nt * 8 + g];
                    mma_tf32(o[nt], pa, vb);
                }
            }
            __syncwarp();
        }

        // store unnormalized partials + (m, l)
        const size_t pbase = ((size_t)s * BB + b) * TT;
        #pragma unroll
        for (int nt = 0; nt < 8; nt++) {
            int col = nt * 8 + 2 * t;
            *(float2*)&g_po[(pbase + gi0) * HH + col] = make_float2(o[nt][0], o[nt][1]);
            *(float2*)&g_po[(pbase + gi1) * HH + col] = make_float2(o[nt][2], o[nt][3]);
        }
        if (t == 0) {
            g_pm[pbase + gi0] = m0r;  g_pl[pbase + gi0] = l0r;
            g_pm[pbase + gi1] = m1r;  g_pl[pbase + gi1] = l1r;
        }
    }
}

// ---------------------------------------------------------------------------
// Combine 4 split-K partials
// ---------------------------------------------------------------------------
__global__ __launch_bounds__(256) void combine_kernel(float* __restrict__ out)
{
    int gid = blockIdx.x * 256 + threadIdx.x;     // < 262144
    int r   = gid >> 4;
    int c4  = (gid & 15) * 4;
    float m[4], lv[4];
    #pragma unroll
    for (int i = 0; i < 4; i++) { m[i] = g_pm[(size_t)i * MM + r]; lv[i] = g_pl[(size_t)i * MM + r]; }
    float Mx = fmaxf(fmaxf(m[0], m[1]), fmaxf(m[2], m[3]));
    float wsum = 0.f;
    float wv[4];
    #pragma unroll
    for (int i = 0; i < 4; i++) { wv[i] = __expf(m[i] - Mx); wsum += wv[i] * lv[i]; }
    float inv = 1.f / wsum;
    float4 acc = make_float4(0.f, 0.f, 0.f, 0.f);
    #pragma unroll
    for (int i = 0; i < 4; i++) {
        float4 oi = *(const float4*)&g_po[((size_t)i * MM + r) * HH + c4];
        acc.x += wv[i] * oi.x; acc.y += wv[i] * oi.y;
        acc.z += wv[i] * oi.z; acc.w += wv[i] * oi.w;
    }
    acc.x *= inv; acc.y *= inv; acc.z *= inv; acc.w *= inv;
    *(float4*)&out[(size_t)r * HH + c4] = acc;
}

// ---------------------------------------------------------------------------
// launch
// ---------------------------------------------------------------------------
extern "C" void kernel_launch(void* const* d_in, const int* in_sizes, int n_in,
                              void* d_out, int out_size)
{
    const float* x     = (const float*)d_in[0];
    const float* Wq    = (const float*)d_in[1];
    const float* Wk    = (const float*)d_in[2];
    const float* Wv    = (const float*)d_in[3];
    const float* rbias = (const float*)d_in[4];
    // d_in[5] (allowed) reconstructed from rbias + indices
    float* out = (float*)d_out;

    cudaFuncSetAttribute(proj_mma_kernel, cudaFuncAttributeMaxDynamicSharedMemorySize, PROJ_SMEM);
    cudaFuncSetAttribute(attn_kernel, cudaFuncAttributeMaxDynamicSharedMemorySize, ATTN_SMEM);

    wsplit_kernel<<<192, 256>>>(Wq, Wk, Wv);
    proj_mma_kernel<<<MM / 64, 256, PROJ_SMEM>>>(x);
    attn_kernel<<<256, 256, ATTN_SMEM>>>(rbias);
    combine_kernel<<<1024, 256>>>(out);
}

// round 16
// speedup vs baseline: 1.5363x; 1.5363x over previous
#include <cuda_runtime.h>
#include <math_constants.h>
#include <cstdint>

#define BB 8
#define TT 2048
#define CC 1024
#define HH 64
#define MM (BB*TT)          // 16384 rows

// scratch (device globals — no allocation allowed)
__device__ float g_q[(size_t)MM*HH];
__device__ float g_k[(size_t)MM*HH];
__device__ float g_v[(size_t)MM*HH];
// tf32 weights, transposed: g_wt[(o*64+n)*1024 + k], o in {q,k,v}
__device__ __align__(16) uint32_t g_wt[3*64*1024];
// split-K attention partials (4 splits)
__device__ float g_po[4*(size_t)MM*HH];
__device__ float g_pm[4*MM];
__device__ float g_pl[4*MM];

// ---------------------------------------------------------------------------
// mma.sync wrappers (plain PTX, sm_80+, works on sm_103 non-'a' target)
// ---------------------------------------------------------------------------
__device__ __forceinline__ void mma_tf32(float* c, const uint32_t* a, const uint32_t* b) {
    asm volatile(
        "mma.sync.aligned.m16n8k8.row.col.f32.tf32.tf32.f32 "
        "{%0,%1,%2,%3},{%4,%5,%6,%7},{%8,%9},{%0,%1,%2,%3};"
        : "+f"(c[0]), "+f"(c[1]), "+f"(c[2]), "+f"(c[3])
        : "r"(a[0]), "r"(a[1]), "r"(a[2]), "r"(a[3]), "r"(b[0]), "r"(b[1]));
}
__device__ __forceinline__ uint32_t f2tf32(float f) {
    uint32_t r;
    asm("cvt.rna.tf32.f32 %0, %1;" : "=r"(r) : "f"(f));
    return r;
}
__device__ __forceinline__ uint32_t smem_to_u32(const void* smem_ptr) {
    uint32_t addr;
    asm("{ .reg .u64 tmp; cvta.to.shared.u64 tmp, %1; cvt.u32.u64 %0, tmp; }"
        : "=r"(addr) : "l"(smem_ptr));
    return addr;
}
#define CP_ASYNC16(saddr, gptr) \
    asm volatile("cp.async.cg.shared.global [%0], [%1], 16;" \
                 :: "r"(saddr), "l"(gptr) : "memory")
#define CP_COMMIT() asm volatile("cp.async.commit_group;" ::: "memory")
#define CP_WAIT0()  asm volatile("cp.async.wait_group 0;" ::: "memory")

// ---------------------------------------------------------------------------
// Weight prep: W[1024,64] (x3) -> tf32, transposed [n][k] (coalesced both sides)
// ---------------------------------------------------------------------------
__global__ __launch_bounds__(256) void wsplit_kernel(
    const float* __restrict__ Wq, const float* __restrict__ Wk, const float* __restrict__ Wv)
{
    __shared__ uint32_t tsm[32][33];
    const int o   = blockIdx.x >> 6;
    const int rem = blockIdx.x & 63;
    const int kt  = rem & 31;
    const int nt2 = rem >> 5;
    const int k0  = kt * 32;
    const int n0  = nt2 * 32;
    const int tx  = threadIdx.x & 31;
    const int ty  = threadIdx.x >> 5;
    const float* W = (o == 0) ? Wq : ((o == 1) ? Wk : Wv);

    #pragma unroll
    for (int i = 0; i < 4; i++) {
        int k = k0 + ty + i * 8;
        tsm[ty + i * 8][tx] = f2tf32(W[(size_t)k * 64 + n0 + tx]);
    }
    __syncthreads();
    #pragma unroll
    for (int i = 0; i < 4; i++) {
        int n = n0 + ty + i * 8;
        g_wt[((size_t)o * 64 + n) * 1024 + k0 + tx] = tsm[tx][ty + i * 8];
    }
}

// ---------------------------------------------------------------------------
// Projection via single-pass tf32 mma.sync:
//   q|k|v[M,64] = x[M,1024] @ W[1024,64]   (both operands tf32)
// 256 CTAs x 256 threads (8 warps: 4M x 2N). CTA owns 64 rows; warp (wm,wn)
// owns rows wm*16..+15 x cols wn*96..+95. K in 16 chunks of 64; A prefetched
// in regs. smem (u32, pitch 68 -> conflict-free frags):
//   As[64][68] @0 (17408B), Bs[192][68] @17408 (52224B) -> 69632B.
// ---------------------------------------------------------------------------
#define PROJ_SMEM 69632

__global__ __launch_bounds__(256, 2) void proj_mma_kernel(const float* __restrict__ x)
{
    extern __shared__ char psm[];
    uint32_t* As = (uint32_t*)(psm);
    uint32_t* Bs = (uint32_t*)(psm + 17408);

    const int tid = threadIdx.x;
    const int w   = tid >> 5;
    const int l   = tid & 31;
    const int g   = l >> 2;
    const int t   = l & 3;
    const int wm  = w >> 1;
    const int wn  = w & 1;
    const int m0  = blockIdx.x * 64;

    float acc[12][4];
    #pragma unroll
    for (int nt = 0; nt < 12; nt++)
        #pragma unroll
        for (int j = 0; j < 4; j++) acc[nt][j] = 0.f;

    float4 apre[4];
    #pragma unroll
    for (int p = 0; p < 4; p++) {
        int i   = p * 256 + tid;
        int row = i >> 4, c4 = i & 15;
        apre[p] = *(const float4*)&x[(size_t)(m0 + row) * CC + c4 * 4];
    }

    for (int c = 0; c < 16; c++) {
        const int kk = c * 64;
        __syncthreads();

        // stage A (tf32)
        #pragma unroll
        for (int p = 0; p < 4; p++) {
            int i   = p * 256 + tid;
            int row = i >> 4, c4 = i & 15;
            uint4 u;
            u.x = f2tf32(apre[p].x); u.y = f2tf32(apre[p].y);
            u.z = f2tf32(apre[p].z); u.w = f2tf32(apre[p].w);
            *(uint4*)&As[row * 68 + c4 * 4] = u;
        }
        // stage B (pre-converted tf32, linear uint4 copy)
        #pragma unroll
        for (int it = 0; it < 12; it++) {
            int i  = it * 256 + tid;       // 0..3071 uint4s (192 rows x 16)
            int n  = i >> 4, c4 = i & 15;
            *(uint4*)&Bs[n * 68 + c4 * 4] =
                *(const uint4*)&g_wt[(size_t)n * 1024 + kk + c4 * 4];
        }
        __syncthreads();

        if (c < 15) {
            #pragma unroll
            for (int p = 0; p < 4; p++) {
                int i   = p * 256 + tid;
                int row = i >> 4, c4 = i & 15;
                apre[p] = *(const float4*)&x[(size_t)(m0 + row) * CC + kk + 64 + c4 * 4];
            }
        }

        const int arow = wm * 16 + g;
        #pragma unroll
        for (int ks = 0; ks < 8; ks++) {
            uint32_t a[4];
            a[0] = As[(arow    ) * 68 + ks * 8 + t    ];
            a[1] = As[(arow + 8) * 68 + ks * 8 + t    ];
            a[2] = As[(arow    ) * 68 + ks * 8 + t + 4];
            a[3] = As[(arow + 8) * 68 + ks * 8 + t + 4];
            #pragma unroll
            for (int nt = 0; nt < 12; nt++) {
                const int brow = wn * 96 + nt * 8 + g;
                uint32_t b[2];
                b[0] = Bs[brow * 68 + ks * 8 + t    ];
                b[1] = Bs[brow * 68 + ks * 8 + t + 4];
                mma_tf32(acc[nt], a, b);
            }
        }
    }

    const int r0 = m0 + wm * 16 + g;
    #pragma unroll
    for (int nt = 0; nt < 12; nt++) {
        int base = wn * 96 + nt * 8;
        int o    = base >> 6;
        int col  = (base & 63) + 2 * t;
        float* dst = (o == 0) ? g_q : ((o == 1) ? g_k : g_v);
        *(float2*)&dst[(size_t)r0 * HH + col]       = make_float2(acc[nt][0], acc[nt][1]);
        *(float2*)&dst[(size_t)(r0 + 8) * HH + col] = make_float2(acc[nt][2], acc[nt][3]);
    }
}

// ---------------------------------------------------------------------------
// Attention (R10 version, verbatim): tf32 mma.sync, 128x64 tiles, cp.async
// pipelined K/V, balanced pairing (p, 15-p) x split-4 -> 256 blocks x 256 thr.
// smem (u32): Qs[128][68] (Q frags + P), Ks[64][68], Vs[64][72],
//             rawK[4096], rawV[4096]  -> 103424 B.
// ---------------------------------------------------------------------------
#define ATTN_SMEM 103424

__global__ __launch_bounds__(256, 2) void attn_kernel(const float* __restrict__ rbias)
{
    extern __shared__ uint32_t sm[];
    uint32_t* Qs   = sm;                       // [128][68], also P staging
    uint32_t* Ks   = sm + 128 * 68;
    uint32_t* Vs   = Ks + 64 * 68;
    uint32_t* rawK = Vs + 64 * 72;
    uint32_t* rawV = rawK + 4096;
    const uint32_t smem_base = smem_to_u32(sm);
    const uint32_t rawK_addr = smem_base + 17664u * 4u;
    const uint32_t rawV_addr = rawK_addr + 16384u;

    const int tid   = threadIdx.x;
    const int w     = tid >> 5;
    const int l     = tid & 31;
    const int g     = l >> 2;
    const int t     = l & 3;
    const int s     = blockIdx.x & 3;
    const int idx   = blockIdx.x >> 2;
    const int pairp = idx >> 3;        // 0..7
    const int b     = idx & 7;

    const float* qg = g_q + (size_t)b * TT * HH;
    const float* kg = g_k + (size_t)b * TT * HH;
    const float* vg = g_v + (size_t)b * TT * HH;
    const float scale = 0.03125f;   // C^-0.5

    for (int rep = 0; rep < 2; rep++) {
        const int itile = rep ? (15 - pairp) : pairp;
        const int i0    = itile * 128;
        const int nfull = 2 * itile + 2;
        const int jt_begin = (s * nfull) >> 2;
        const int jt_end   = ((s + 1) * nfull) >> 2;

        __syncthreads();   // Qs (P) reuse across reps
        #pragma unroll
        for (int it = 0; it < 8; it++) {
            int i = it * 256 + tid;
            int row = i >> 4, c4 = i & 15;
            float4 v = *(const float4*)&qg[(size_t)(i0 + row) * HH + c4 * 4];
            uint4 u;
            u.x = f2tf32(v.x); u.y = f2tf32(v.y); u.z = f2tf32(v.z); u.w = f2tf32(v.w);
            *(uint4*)&Qs[row * 68 + c4 * 4] = u;
        }
        __syncthreads();

        uint32_t qa[8][4];
        {
            const int qrow = w * 16 + g;
            #pragma unroll
            for (int ks = 0; ks < 8; ks++) {
                qa[ks][0] = Qs[(qrow    ) * 68 + ks * 8 + t    ];
                qa[ks][1] = Qs[(qrow + 8) * 68 + ks * 8 + t    ];
                qa[ks][2] = Qs[(qrow    ) * 68 + ks * 8 + t + 4];
                qa[ks][3] = Qs[(qrow + 8) * 68 + ks * 8 + t + 4];
            }
        }

        float o[8][4];
        #pragma unroll
        for (int nt = 0; nt < 8; nt++)
            #pragma unroll
            for (int j = 0; j < 4; j++) o[nt][j] = 0.f;
        float m0r = -CUDART_INF_F, m1r = -CUDART_INF_F, l0r = 0.f, l1r = 0.f;

        const int gi0 = i0 + w * 16 + g;
        const int gi1 = gi0 + 8;
        const int prow0 = (w * 16 + g) * 68;
        const int prow1 = prow0 + 8 * 68;

        if (jt_begin < jt_end) {
            const float* kp = kg + (size_t)jt_begin * 64 * HH;
            const float* vp = vg + (size_t)jt_begin * 64 * HH;
            #pragma unroll
            for (int p = 0; p < 4; p++) {
                int i = p * 256 + tid;
                CP_ASYNC16(rawK_addr + i * 16, kp + i * 4);
                CP_ASYNC16(rawV_addr + i * 16, vp + i * 4);
            }
            CP_COMMIT();
        }

        for (int jt = jt_begin; jt < jt_end; jt++) {
            const int j0 = jt * 64;
            CP_WAIT0();
            __syncthreads();
            #pragma unroll
            for (int it = 0; it < 4; it++) {
                int i = it * 256 + tid;
                int row = i >> 4, c4 = i & 15;
                uint4 kq = *(uint4*)&rawK[i * 4];
                uint4 ko;
                ko.x = f2tf32(__uint_as_float(kq.x)); ko.y = f2tf32(__uint_as_float(kq.y));
                ko.z = f2tf32(__uint_as_float(kq.z)); ko.w = f2tf32(__uint_as_float(kq.w));
                *(uint4*)&Ks[row * 68 + c4 * 4] = ko;
                uint4 vq = *(uint4*)&rawV[i * 4];
                uint4 vo;
                vo.x = f2tf32(__uint_as_float(vq.x)); vo.y = f2tf32(__uint_as_float(vq.y));
                vo.z = f2tf32(__uint_as_float(vq.z)); vo.w = f2tf32(__uint_as_float(vq.w));
                *(uint4*)&Vs[row * 72 + c4 * 4] = vo;
            }
            __syncthreads();
            if (jt + 1 < jt_end) {
                const float* kp = kg + (size_t)(jt + 1) * 64 * HH;
                const float* vp = vg + (size_t)(jt + 1) * 64 * HH;
                #pragma unroll
                for (int p = 0; p < 4; p++) {
                    int i = p * 256 + tid;
                    CP_ASYNC16(rawK_addr + i * 16, kp + i * 4);
                    CP_ASYNC16(rawV_addr + i * 16, vp + i * 4);
                }
                CP_COMMIT();
            }

            // S = Q K^T
            float sv[8][4];
            #pragma unroll
            for (int nt = 0; nt < 8; nt++) {
                sv[nt][0] = 0.f; sv[nt][1] = 0.f; sv[nt][2] = 0.f; sv[nt][3] = 0.f;
                #pragma unroll
                for (int ks = 0; ks < 8; ks++) {
                    uint32_t kb[2];
                    kb[0] = Ks[(nt * 8 + g) * 68 + ks * 8 + t    ];
                    kb[1] = Ks[(nt * 8 + g) * 68 + ks * 8 + t + 4];
                    mma_tf32(sv[nt], qa[ks], kb);
                }
            }

            // bias + mask + row max
            float rm0 = -CUDART_INF_F, rm1 = -CUDART_INF_F;
            #pragma unroll
            for (int nt = 0; nt < 8; nt++) {
                int cj = j0 + nt * 8 + 2 * t;
                float2 rb0 = *(const float2*)&rbias[(size_t)gi0 * TT + cj];
                float2 rb1 = *(const float2*)&rbias[(size_t)gi1 * TT + cj];
                bool ok;
                ok = (cj     < gi0 && rb0.x > 0.f) || (cj     == gi0);
                sv[nt][0] = ok ? fmaf(sv[nt][0], scale, rb0.x) : -CUDART_INF_F;
                ok = (cj + 1 < gi0 && rb0.y > 0.f) || (cj + 1 == gi0);
                sv[nt][1] = ok ? fmaf(sv[nt][1], scale, rb0.y) : -CUDART_INF_F;
                ok = (cj     < gi1 && rb1.x > 0.f) || (cj     == gi1);
                sv[nt][2] = ok ? fmaf(sv[nt][2], scale, rb1.x) : -CUDART_INF_F;
                ok = (cj + 1 < gi1 && rb1.y > 0.f) || (cj + 1 == gi1);
                sv[nt][3] = ok ? fmaf(sv[nt][3], scale, rb1.y) : -CUDART_INF_F;
                rm0 = fmaxf(rm0, fmaxf(sv[nt][0], sv[nt][1]));
                rm1 = fmaxf(rm1, fmaxf(sv[nt][2], sv[nt][3]));
            }
            rm0 = fmaxf(rm0, __shfl_xor_sync(0xffffffffu, rm0, 1));
            rm0 = fmaxf(rm0, __shfl_xor_sync(0xffffffffu, rm0, 2));
            rm1 = fmaxf(rm1, __shfl_xor_sync(0xffffffffu, rm1, 1));
            rm1 = fmaxf(rm1, __shfl_xor_sync(0xffffffffu, rm1, 2));

            float mn0 = fmaxf(m0r, rm0), mn1 = fmaxf(m1r, rm1);
            float mu0 = (mn0 == -CUDART_INF_F) ? 0.f : mn0;
            float mu1 = (mn1 == -CUDART_INF_F) ? 0.f : mn1;
            float a0 = __expf(m0r - mu0), a1 = __expf(m1r - mu1);
            float rs0 = 0.f, rs1 = 0.f;
            #pragma unroll
            for (int nt = 0; nt < 8; nt++) {
                sv[nt][0] = __expf(sv[nt][0] - mu0); rs0 += sv[nt][0];
                sv[nt][1] = __expf(sv[nt][1] - mu0); rs0 += sv[nt][1];
                sv[nt][2] = __expf(sv[nt][2] - mu1); rs1 += sv[nt][2];
                sv[nt][3] = __expf(sv[nt][3] - mu1); rs1 += sv[nt][3];
            }
            rs0 += __shfl_xor_sync(0xffffffffu, rs0, 1);
            rs0 += __shfl_xor_sync(0xffffffffu, rs0, 2);
            rs1 += __shfl_xor_sync(0xffffffffu, rs1, 1);
            rs1 += __shfl_xor_sync(0xffffffffu, rs1, 2);
            l0r = l0r * a0 + rs0;  m0r = mn0;
            l1r = l1r * a1 + rs1;  m1r = mn1;

            #pragma unroll
            for (int nt = 0; nt < 8; nt++) {
                o[nt][0] *= a0; o[nt][1] *= a0; o[nt][2] *= a1; o[nt][3] *= a1;
                int pc = nt * 8 + 2 * t;
                Qs[prow0 + pc]     = f2tf32(sv[nt][0]);
                Qs[prow0 + pc + 1] = f2tf32(sv[nt][1]);
                Qs[prow1 + pc]     = f2tf32(sv[nt][2]);
                Qs[prow1 + pc + 1] = f2tf32(sv[nt][3]);
            }
            __syncwarp();

            // O += P @ V
            #pragma unroll
            for (int ks = 0; ks < 8; ks++) {
                uint32_t pa[4];
                pa[0] = Qs[prow0 + ks * 8 + t    ];
                pa[1] = Qs[prow1 + ks * 8 + t    ];
                pa[2] = Qs[prow0 + ks * 8 + t + 4];
                pa[3] = Qs[prow1 + ks * 8 + t + 4];
                #pragma unroll
                for (int nt = 0; nt < 8; nt++) {
                    uint32_t vb[2];
                    vb[0] = Vs[(ks * 8 + t    ) * 72 + nt * 8 + g];
                    vb[1] = Vs[(ks * 8 + t + 4) * 72 + nt * 8 + g];
                    mma_tf32(o[nt], pa, vb);
                }
            }
            __syncwarp();
        }

        // store unnormalized partials + (m, l)
        const size_t pbase = ((size_t)s * BB + b) * TT;
        #pragma unroll
        for (int nt = 0; nt < 8; nt++) {
            int col = nt * 8 + 2 * t;
            *(float2*)&g_po[(pbase + gi0) * HH + col] = make_float2(o[nt][0], o[nt][1]);
            *(float2*)&g_po[(pbase + gi1) * HH + col] = make_float2(o[nt][2], o[nt][3]);
        }
        if (t == 0) {
            g_pm[pbase + gi0] = m0r;  g_pl[pbase + gi0] = l0r;
            g_pm[pbase + gi1] = m1r;  g_pl[pbase + gi1] = l1r;
        }
    }
}

// ---------------------------------------------------------------------------
// Combine 4 split-K partials
// ---------------------------------------------------------------------------
__global__ __launch_bounds__(256) void combine_kernel(float* __restrict__ out)
{
    int gid = blockIdx.x * 256 + threadIdx.x;     // < 262144
    int r   = gid >> 4;
    int c4  = (gid & 15) * 4;
    float m[4], lv[4];
    #pragma unroll
    for (int i = 0; i < 4; i++) { m[i] = g_pm[(size_t)i * MM + r]; lv[i] = g_pl[(size_t)i * MM + r]; }
    float Mx = fmaxf(fmaxf(m[0], m[1]), fmaxf(m[2], m[3]));
    float wsum = 0.f;
    float wv[4];
    #pragma unroll
    for (int i = 0; i < 4; i++) { wv[i] = __expf(m[i] - Mx); wsum += wv[i] * lv[i]; }
    float inv = 1.f / wsum;
    float4 acc = make_float4(0.f, 0.f, 0.f, 0.f);
    #pragma unroll
    for (int i = 0; i < 4; i++) {
        float4 oi = *(const float4*)&g_po[((size_t)i * MM + r) * HH + c4];
        acc.x += wv[i] * oi.x; acc.y += wv[i] * oi.y;
        acc.z += wv[i] * oi.z; acc.w += wv[i] * oi.w;
    }
    acc.x *= inv; acc.y *= inv; acc.z *= inv; acc.w *= inv;
    *(float4*)&out[(size_t)r * HH + c4] = acc;
}

// ---------------------------------------------------------------------------
// launch
// ---------------------------------------------------------------------------
extern "C" void kernel_launch(void* const* d_in, const int* in_sizes, int n_in,
                              void* d_out, int out_size)
{
    const float* x     = (const float*)d_in[0];
    const float* Wq    = (const float*)d_in[1];
    const float* Wk    = (const float*)d_in[2];
    const float* Wv    = (const float*)d_in[3];
    const float* rbias = (const float*)d_in[4];
    // d_in[5] (allowed) reconstructed from rbias + indices
    float* out = (float*)d_out;

    cudaFuncSetAttribute(proj_mma_kernel, cudaFuncAttributeMaxDynamicSharedMemorySize, PROJ_SMEM);
    cudaFuncSetAttribute(attn_kernel, cudaFuncAttributeMaxDynamicSharedMemorySize, ATTN_SMEM);

    wsplit_kernel<<<192, 256>>>(Wq, Wk, Wv);
    proj_mma_kernel<<<MM / 64, 256, PROJ_SMEM>>>(x);
    attn_kernel<<<256, 256, ATTN_SMEM>>>(rbias);
    combine_kernel<<<1024, 256>>>(out);
}